// round 2
// baseline (speedup 1.0000x reference)
#include <cuda_runtime.h>
#include <cstdint>

#define N_PAIRS 500000
#define LMAX    4
#define NM      16
#define HID     32
#define NSPEC   4

// Scratch (allocation-free rule: __device__ globals)
__device__ int d_count[NSPEC];
__device__ int d_cursor[NSPEC];
__device__ int d_off[NSPEC + 1];
__device__ int d_sorted[N_PAIRS];
__device__ int d_stride;   // 1 = species stored as int32, 2 = int64 (read low words)

// ---------------- dtype detection + init ----------------

__global__ void k_init(const int* __restrict__ sp32) {
    __shared__ int any_nonzero;
    int t = threadIdx.x;
    if (t == 0) any_nonzero = 0;
    if (t < NSPEC) d_count[t] = 0;
    __syncthreads();
    // probe odd words 1,3,...,511 (all within buffer for either dtype)
    if (sp32[2 * t + 1] != 0) atomicOr(&any_nonzero, 1);
    __syncthreads();
    if (t == 0) d_stride = any_nonzero ? 1 : 2;
}

// ---------------- sort-by-species pipeline ----------------

__global__ void k_hist(const int* __restrict__ sp32) {
    __shared__ int cnt[NSPEC];
    int tid = threadIdx.x;
    if (tid < NSPEC) cnt[tid] = 0;
    __syncthreads();
    const int stride = d_stride;
    int i = blockIdx.x * blockDim.x + tid;
    if (i < N_PAIRS) {
        int sp = sp32[i * stride] & 3;
        atomicAdd(&cnt[sp], 1);
    }
    __syncthreads();
    if (tid < NSPEC && cnt[tid] > 0) atomicAdd(&d_count[tid], cnt[tid]);
}

__global__ void k_offsets() {
    int acc = 0;
    d_off[0] = 0;
    for (int s = 0; s < NSPEC; ++s) {
        acc += d_count[s];
        d_off[s + 1] = acc;
    }
    for (int s = 0; s < NSPEC; ++s) d_cursor[s] = d_off[s];
}

__global__ void k_scatter(const int* __restrict__ sp32) {
    __shared__ int cnt[NSPEC];
    __shared__ int base[NSPEC];
    int tid = threadIdx.x;
    if (tid < NSPEC) cnt[tid] = 0;
    __syncthreads();
    const int stride = d_stride;
    int i = blockIdx.x * blockDim.x + tid;
    int sp = 0;
    if (i < N_PAIRS) {
        sp = sp32[i * stride] & 3;
        atomicAdd(&cnt[sp], 1);
    }
    __syncthreads();
    if (tid < NSPEC) {
        base[tid] = (cnt[tid] > 0) ? atomicAdd(&d_cursor[tid], cnt[tid]) : 0;
        cnt[tid] = 0;   // reuse as local rank cursor
    }
    __syncthreads();
    if (i < N_PAIRS) {
        int r = atomicAdd(&cnt[sp], 1);
        d_sorted[base[sp] + r] = i;
    }
}

// ---------------- main MLP kernel ----------------

__device__ __forceinline__ float silu(float v) {
    return v * (1.0f / (1.0f + __expf(-v)));
}

// One fused dense layer: out[OUT] = (optionally silu)(in[IN] @ W[IN][OUT])
// W row-major (o contiguous), read as float4 broadcasts from smem.
template <int IN, int OUT, bool ACT>
__device__ __forceinline__ void layer(const float* __restrict__ w,
                                      const float* __restrict__ in,
                                      float* __restrict__ out) {
#pragma unroll
    for (int o4 = 0; o4 < OUT / 4; ++o4) {
        float4 a = make_float4(0.f, 0.f, 0.f, 0.f);
#pragma unroll
        for (int i = 0; i < IN; ++i) {
            float4 wv = *reinterpret_cast<const float4*>(w + i * OUT + o4 * 4);
            a.x = fmaf(in[i], wv.x, a.x);
            a.y = fmaf(in[i], wv.y, a.y);
            a.z = fmaf(in[i], wv.z, a.z);
            a.w = fmaf(in[i], wv.w, a.w);
        }
        if (ACT) { a.x = silu(a.x); a.y = silu(a.y); a.z = silu(a.z); a.w = silu(a.w); }
        out[o4 * 4 + 0] = a.x;
        out[o4 * 4 + 1] = a.y;
        out[o4 * 4 + 2] = a.z;
        out[o4 * 4 + 3] = a.w;
    }
}

// Per-species smem weight block layout (3072 floats):
// [0,512) W1 (16x32), [512,1536) W2 (32x32), [1536,2560) W3 (32x32), [2560,3072) W4 (32x16)
#define SPBLK 3072

__global__ void __launch_bounds__(256)
k_mlp(const float* __restrict__ xg,
      const float* __restrict__ W1, const float* __restrict__ W2,
      const float* __restrict__ W3, const float* __restrict__ W4,
      float* __restrict__ out) {
    const int l = blockIdx.y;
    __shared__ float wsm[NSPEC * SPBLK];   // 48 KB

    // cooperative weight load for this l (all 4 species)
    for (int t = threadIdx.x; t < NSPEC * SPBLK; t += blockDim.x) {
        int s = t / SPBLK;
        int j = t - s * SPBLK;
        float v;
        if (j < 512)        v = W1[(l * NSPEC + s) * 512  + j];
        else if (j < 1536)  v = W2[(l * NSPEC + s) * 1024 + (j - 512)];
        else if (j < 2560)  v = W3[(l * NSPEC + s) * 1024 + (j - 1536)];
        else                v = W4[(l * NSPEC + s) * 512  + (j - 2560)];
        wsm[t] = v;
    }
    __syncthreads();

    const int off1 = d_off[1], off2 = d_off[2], off3 = d_off[3];

    for (int p = blockIdx.x * blockDim.x + threadIdx.x; p < N_PAIRS;
         p += gridDim.x * blockDim.x) {
        const int idx = d_sorted[p];
        // species from sorted position (bucket boundaries) — warp-uniform after sort
        const int sp = (p >= off2) ? ((p >= off3) ? 3 : 2) : ((p >= off1) ? 1 : 0);
        const float* w = &wsm[sp * SPBLK];

        float a[HID], b[HID];

        // load x[16] (64B contiguous per thread)
        const float4* xin = reinterpret_cast<const float4*>(xg + ((size_t)idx * LMAX + l) * NM);
#pragma unroll
        for (int q = 0; q < 4; ++q) {
            float4 v = xin[q];
            a[q * 4 + 0] = v.x; a[q * 4 + 1] = v.y; a[q * 4 + 2] = v.z; a[q * 4 + 3] = v.w;
        }

        layer<NM,  HID, true >(w,          a, b);   // L1 + silu
        layer<HID, HID, true >(w + 512,    b, a);   // L2 + silu
        layer<HID, HID, true >(w + 1536,   a, b);   // L3 + silu
        layer<HID, NM,  false>(w + 2560,   b, a);   // L4

        float4* op = reinterpret_cast<float4*>(out + ((size_t)idx * LMAX + l) * NM);
#pragma unroll
        for (int q = 0; q < 4; ++q)
            op[q] = make_float4(a[q * 4 + 0], a[q * 4 + 1], a[q * 4 + 2], a[q * 4 + 3]);
    }
}

// ---------------- launch ----------------

extern "C" void kernel_launch(void* const* d_in, const int* in_sizes, int n_in,
                              void* d_out, int out_size) {
    const float* x   = (const float*)d_in[0];
    const int*   sp  = (const int*)d_in[1];   // int32 or int64 — detected on device
    const float* W1  = (const float*)d_in[2];
    const float* W2  = (const float*)d_in[3];
    const float* W3  = (const float*)d_in[4];
    const float* W4  = (const float*)d_in[5];
    float*       out = (float*)d_out;

    const int nblk = (N_PAIRS + 255) / 256;

    k_init<<<1, 256>>>(sp);
    k_hist<<<nblk, 256>>>(sp);
    k_offsets<<<1, 1>>>();
    k_scatter<<<nblk, 256>>>(sp);

    dim3 grid(76, LMAX);
    k_mlp<<<grid, 256>>>(x, W1, W2, W3, W4, out);
}

// round 3
// speedup vs baseline: 1.3947x; 1.3947x over previous
#include <cuda_runtime.h>
#include <cstdint>

#define N_PAIRS 500000
#define LMAX    4
#define NM      16
#define HID     32
#define NSPEC   4

// Scratch (allocation-free rule: __device__ globals)
__device__ int d_count[NSPEC];
__device__ int d_cursor[NSPEC];
__device__ int d_off[NSPEC + 1];
__device__ int d_sorted[N_PAIRS];
__device__ int d_stride;   // 1 = species stored as int32, 2 = int64 (read low words)

// ---------------- dtype detection + init ----------------

__global__ void k_init(const int* __restrict__ sp32) {
    __shared__ int any_nonzero;
    int t = threadIdx.x;
    if (t == 0) any_nonzero = 0;
    if (t < NSPEC) d_count[t] = 0;
    __syncthreads();
    // probe odd words 1,3,...,511 (within buffer for either dtype)
    if (sp32[2 * t + 1] != 0) atomicOr(&any_nonzero, 1);
    __syncthreads();
    if (t == 0) d_stride = any_nonzero ? 1 : 2;
}

// ---------------- sort-by-species pipeline ----------------

__global__ void k_hist(const int* __restrict__ sp32) {
    __shared__ int cnt[NSPEC];
    int tid = threadIdx.x;
    if (tid < NSPEC) cnt[tid] = 0;
    __syncthreads();
    const int stride = d_stride;
    int i = blockIdx.x * blockDim.x + tid;
    if (i < N_PAIRS) {
        int sp = sp32[i * stride] & 3;
        atomicAdd(&cnt[sp], 1);
    }
    __syncthreads();
    if (tid < NSPEC && cnt[tid] > 0) atomicAdd(&d_count[tid], cnt[tid]);
}

__global__ void k_offsets() {
    int acc = 0;
    d_off[0] = 0;
    for (int s = 0; s < NSPEC; ++s) {
        acc += d_count[s];
        d_off[s + 1] = acc;
    }
    for (int s = 0; s < NSPEC; ++s) d_cursor[s] = d_off[s];
}

__global__ void k_scatter(const int* __restrict__ sp32) {
    __shared__ int cnt[NSPEC];
    __shared__ int base[NSPEC];
    int tid = threadIdx.x;
    if (tid < NSPEC) cnt[tid] = 0;
    __syncthreads();
    const int stride = d_stride;
    int i = blockIdx.x * blockDim.x + tid;
    int sp = 0;
    if (i < N_PAIRS) {
        sp = sp32[i * stride] & 3;
        atomicAdd(&cnt[sp], 1);
    }
    __syncthreads();
    if (tid < NSPEC) {
        base[tid] = (cnt[tid] > 0) ? atomicAdd(&d_cursor[tid], cnt[tid]) : 0;
        cnt[tid] = 0;   // reuse as local rank cursor
    }
    __syncthreads();
    if (i < N_PAIRS) {
        int r = atomicAdd(&cnt[sp], 1);
        d_sorted[base[sp] + r] = i;
    }
}

// ---------------- packed f32x2 helpers ----------------

__device__ __forceinline__ uint64_t pack2(float v) {
    uint64_t r;
    unsigned u = __float_as_uint(v);
    asm("mov.b64 %0, {%1, %1};" : "=l"(r) : "r"(u));
    return r;
}

__device__ __forceinline__ void unpack2(uint64_t p, float& a, float& b) {
    unsigned lo, hi;
    asm("mov.b64 {%0, %1}, %2;" : "=r"(lo), "=r"(hi) : "l"(p));
    a = __uint_as_float(lo);
    b = __uint_as_float(hi);
}

// d += a * b, two fp32 lanes per instruction (FFMA2 — ptxas never emits this from C++)
__device__ __forceinline__ void fma2(uint64_t& d, uint64_t a, uint64_t b) {
    asm("fma.rn.f32x2 %0, %1, %2, %0;" : "+l"(d) : "l"(a), "l"(b));
}

__device__ __forceinline__ float silu(float v) {
    return __fdividef(v, 1.0f + __expf(-v));
}

// ---------------- main MLP kernel ----------------

// One fused dense layer using packed f32x2 FMAs.
// W row-major [IN][OUT] in smem (16B-aligned rows). i-outer / o-inner:
// one pack per input, 16 (or 8) independent packed accumulator chains.
template <int IN, int OUT, bool ACT>
__device__ __forceinline__ void layer2(const float* __restrict__ w,
                                       const float* __restrict__ in,
                                       float* __restrict__ out) {
    uint64_t acc[OUT / 2];
#pragma unroll
    for (int o = 0; o < OUT / 2; ++o) acc[o] = 0ull;   // {+0.f, +0.f}

#pragma unroll
    for (int i = 0; i < IN; ++i) {
        const uint64_t dup = pack2(in[i]);
        const ulonglong2* wrow = reinterpret_cast<const ulonglong2*>(w + i * OUT);
#pragma unroll
        for (int o4 = 0; o4 < OUT / 4; ++o4) {
            ulonglong2 wv = wrow[o4];           // LDS.128 broadcast (warp-uniform addr)
            fma2(acc[o4 * 2 + 0], dup, wv.x);
            fma2(acc[o4 * 2 + 1], dup, wv.y);
        }
    }

#pragma unroll
    for (int o2 = 0; o2 < OUT / 2; ++o2) {
        float v0, v1;
        unpack2(acc[o2], v0, v1);
        if (ACT) { v0 = silu(v0); v1 = silu(v1); }
        out[o2 * 2 + 0] = v0;
        out[o2 * 2 + 1] = v1;
    }
}

// Per-species smem weight block layout (3072 floats):
// [0,512) W1 (16x32), [512,1536) W2 (32x32), [1536,2560) W3 (32x32), [2560,3072) W4 (32x16)
#define SPBLK 3072

__global__ void __launch_bounds__(256, 2)
k_mlp(const float* __restrict__ xg,
      const float* __restrict__ W1, const float* __restrict__ W2,
      const float* __restrict__ W3, const float* __restrict__ W4,
      float* __restrict__ out) {
    const int l = blockIdx.y;
    __shared__ float wsm[NSPEC * SPBLK];   // 48 KB

    // cooperative weight load for this l (all 4 species)
    for (int t = threadIdx.x; t < NSPEC * SPBLK; t += blockDim.x) {
        int s = t / SPBLK;
        int j = t - s * SPBLK;
        float v;
        if (j < 512)        v = W1[(l * NSPEC + s) * 512  + j];
        else if (j < 1536)  v = W2[(l * NSPEC + s) * 1024 + (j - 512)];
        else if (j < 2560)  v = W3[(l * NSPEC + s) * 1024 + (j - 1536)];
        else                v = W4[(l * NSPEC + s) * 512  + (j - 2560)];
        wsm[t] = v;
    }
    __syncthreads();

    const int off1 = d_off[1], off2 = d_off[2], off3 = d_off[3];

    for (int p = blockIdx.x * blockDim.x + threadIdx.x; p < N_PAIRS;
         p += gridDim.x * blockDim.x) {
        const int idx = d_sorted[p];
        // species from sorted position (bucket boundaries) — warp-uniform after sort
        const int sp = (p >= off2) ? ((p >= off3) ? 3 : 2) : ((p >= off1) ? 1 : 0);
        const float* w = &wsm[sp * SPBLK];

        float a[HID], b[HID];

        // load x[16] (64B contiguous per thread)
        const float4* xin = reinterpret_cast<const float4*>(xg + ((size_t)idx * LMAX + l) * NM);
#pragma unroll
        for (int q = 0; q < 4; ++q) {
            float4 v = xin[q];
            a[q * 4 + 0] = v.x; a[q * 4 + 1] = v.y; a[q * 4 + 2] = v.z; a[q * 4 + 3] = v.w;
        }

        layer2<NM,  HID, true >(w,        a, b);   // L1 + silu
        layer2<HID, HID, true >(w + 512,  b, a);   // L2 + silu
        layer2<HID, HID, true >(w + 1536, a, b);   // L3 + silu
        layer2<HID, NM,  false>(w + 2560, b, a);   // L4

        float4* op = reinterpret_cast<float4*>(out + ((size_t)idx * LMAX + l) * NM);
#pragma unroll
        for (int q = 0; q < 4; ++q)
            op[q] = make_float4(a[q * 4 + 0], a[q * 4 + 1], a[q * 4 + 2], a[q * 4 + 3]);
    }
}

// ---------------- launch ----------------

extern "C" void kernel_launch(void* const* d_in, const int* in_sizes, int n_in,
                              void* d_out, int out_size) {
    const float* x   = (const float*)d_in[0];
    const int*   sp  = (const int*)d_in[1];   // int32 or int64 — detected on device
    const float* W1  = (const float*)d_in[2];
    const float* W2  = (const float*)d_in[3];
    const float* W3  = (const float*)d_in[4];
    const float* W4  = (const float*)d_in[5];
    float*       out = (float*)d_out;

    const int nblk = (N_PAIRS + 255) / 256;

    k_init<<<1, 256>>>(sp);
    k_hist<<<nblk, 256>>>(sp);
    k_offsets<<<1, 1>>>();
    k_scatter<<<nblk, 256>>>(sp);

    // 304 CTAs = 2 resident per SM (48KB smem each) — exactly one wave
    dim3 grid(76, LMAX);
    k_mlp<<<grid, 256>>>(x, W1, W2, W3, W4, out);
}